// round 3
// baseline (speedup 1.0000x reference)
#include <cuda_runtime.h>

#define B_TOT    8192
#define T_LEN    512
#define F_IN     24
#define H_DIM    12
#define CHUNK    8
#define EPB      16           // batch elements per block
#define NTHREADS (EPB * 4)    // 64 (4 threads per element, 3 h-rows each)
#define NCHUNK   (T_LEN / CHUNK)
#define XS_STRIDE 28          // padded floats per (tt, elem) row
#define XS_BUF_FLOATS (CHUNK * EPB * XS_STRIDE)
#define SMEM_BYTES (2 * XS_BUF_FLOATS * 4)

typedef unsigned long long u64;

__device__ __forceinline__ unsigned smem_u32(const void* p) {
    return (unsigned)__cvta_generic_to_shared(p);
}
__device__ __forceinline__ void cp_async16(unsigned dst, const void* src) {
    asm volatile("cp.async.cg.shared.global [%0], [%1], 16;\n" :: "r"(dst), "l"(src));
}
__device__ __forceinline__ void cp_commit() {
    asm volatile("cp.async.commit_group;\n" ::: "memory");
}
template <int N> __device__ __forceinline__ void cp_wait() {
    asm volatile("cp.async.wait_group %0;\n" :: "n"(N) : "memory");
}

// ---- packed f32x2 helpers ----
__device__ __forceinline__ u64 pack2(float lo, float hi) {
    u64 d; asm("mov.b64 %0, {%1, %2};" : "=l"(d) : "f"(lo), "f"(hi)); return d;
}
__device__ __forceinline__ void unpack2(u64 d, float& lo, float& hi) {
    asm("mov.b64 {%0, %1}, %2;" : "=f"(lo), "=f"(hi) : "l"(d));
}
__device__ __forceinline__ u64 fma2(u64 a, u64 b, u64 c) {
    u64 d; asm("fma.rn.f32x2 %0, %1, %2, %3;" : "=l"(d) : "l"(a), "l"(b), "l"(c)); return d;
}
__device__ __forceinline__ u64 add2(u64 a, u64 b) {
    u64 d; asm("add.rn.f32x2 %0, %1, %2;" : "=l"(d) : "l"(a), "l"(b)); return d;
}
__device__ __forceinline__ float hadd2(u64 a) {
    float lo, hi; unpack2(a, lo, hi); return lo + hi;
}

// tanh(x) = 1 - 2*rcp(exp(2x)+1); 5 instrs, correct saturation at +/-inf.
__device__ __forceinline__ float tanh_fast(float x) {
    float e;
    asm("ex2.approx.f32 %0, %1;" : "=f"(e) : "f"(x * 2.885390082f));
    float r;
    asm("rcp.approx.f32 %0, %1;" : "=f"(r) : "f"(e + 1.0f));
    return fmaf(-2.0f, r, 1.0f);
}

__global__ void __launch_bounds__(NTHREADS) rnn_fused_kernel(
    const float* __restrict__ x,
    const float* __restrict__ W_ih, const float* __restrict__ b_ih,
    const float* __restrict__ W_hh, const float* __restrict__ b_hh,
    const float* __restrict__ W1,   const float* __restrict__ b1,
    const float* __restrict__ W2,   const float* __restrict__ b2,
    const float* __restrict__ W3,   const float* __restrict__ b3,
    float* __restrict__ out)
{
    extern __shared__ float xs[];  // [2][CHUNK][EPB][XS_STRIDE]
    __shared__ float sW1[144], sW2[144], sb1[12], sb2[12], sW3[12], sb3[1];

    const int tid  = threadIdx.x;
    const int e    = tid >> 2;        // element within block
    const int sub  = tid & 3;         // which 3 h-rows this thread owns
    const int lane = tid & 31;
    const int b    = blockIdx.x * EPB + e;
    const int j0   = sub * 3;

    for (int i = tid; i < 144; i += NTHREADS) { sW1[i] = W1[i]; sW2[i] = W2[i]; }
    if (tid < 12) { sb1[tid] = b1[tid]; sb2[tid] = b2[tid]; sW3[tid] = W3[tid]; }
    if (tid == 0) sb3[0] = b3[0];

    // Per-thread weights, packed along contraction dim.
    u64 wih2[3][F_IN / 2], whh2[3][H_DIM / 2], biasp[3];
    #pragma unroll
    for (int c = 0; c < 3; c++) {
        const int j = j0 + c;
        #pragma unroll
        for (int p = 0; p < F_IN / 2; p++)
            wih2[c][p] = pack2(W_ih[j * F_IN + 2 * p], W_ih[j * F_IN + 2 * p + 1]);
        #pragma unroll
        for (int p = 0; p < H_DIM / 2; p++)
            whh2[c][p] = pack2(W_hh[j * H_DIM + 2 * p], W_hh[j * H_DIM + 2 * p + 1]);
        biasp[c] = pack2(b_ih[j] + b_hh[j], 0.0f);
    }

    // cp.async addressing, all index math compile-time except per-thread bases.
    // Thread (e, sub) loads timesteps {2*sub, 2*sub+1} of element e: 12 x 16B.
    const float* src0 = x + ((long)b * T_LEN + 2 * sub) * F_IN;   // advances by CHUNK*F_IN per chunk
    const unsigned dst0 = smem_u32(xs) + (unsigned)(((2 * sub * EPB + e) * XS_STRIDE) * 4);

    auto load_chunk = [&](int bufidx, int c) {
        const float* s = src0 + (long)c * (CHUNK * F_IN);
        const unsigned d = dst0 + (unsigned)bufidx * (XS_BUF_FLOATS * 4);
        #pragma unroll
        for (int j = 0; j < 12; j++) {
            const int tt_l = j / 6;           // 0 or 1 (compile-time)
            const int q    = j % 6;           // 0..5  (compile-time)
            cp_async16(d + (unsigned)((tt_l * EPB * XS_STRIDE + q * 4) * 4),
                       s + tt_l * F_IN + q * 4);
        }
        cp_commit();
    };

    u64 hp[H_DIM / 2];
    #pragma unroll
    for (int k = 0; k < H_DIM / 2; k++) hp[k] = 0ull;

    const u64 ZERO2 = 0ull;
    const int qbase = lane & ~3;

    load_chunk(0, 0);

    for (int c = 0; c < NCHUNK; c++) {
        __syncthreads();  // everyone done reading the buffer we overwrite
        if (c + 1 < NCHUNK) { load_chunk((c + 1) & 1, c + 1); cp_wait<1>(); }
        else                { cp_wait<0>(); }
        __syncthreads();  // buf[c&1] visible

        const float* buf = xs + (c & 1) * XS_BUF_FLOATS;

        // ---------- Phase A: input projections for all 8 steps (independent) ----------
        float xps[CHUNK][3];
        #pragma unroll
        for (int tt = 0; tt < CHUNK; tt++) {
            const ulonglong2* xr = (const ulonglong2*)(buf + (tt * EPB + e) * XS_STRIDE);
            u64 a0 = biasp[0], a1 = biasp[1], a2 = biasp[2];
            #pragma unroll
            for (int q = 0; q < 6; q++) {
                ulonglong2 v = xr[q];
                a0 = fma2(wih2[0][2 * q + 0], v.x, a0);
                a1 = fma2(wih2[1][2 * q + 0], v.x, a1);
                a2 = fma2(wih2[2][2 * q + 0], v.x, a2);
                a0 = fma2(wih2[0][2 * q + 1], v.y, a0);
                a1 = fma2(wih2[1][2 * q + 1], v.y, a1);
                a2 = fma2(wih2[2][2 * q + 1], v.y, a2);
            }
            xps[tt][0] = hadd2(a0);
            xps[tt][1] = hadd2(a1);
            xps[tt][2] = hadd2(a2);
        }

        // ---------- Phase B: serial recurrence (short chain per step) ----------
        #pragma unroll
        for (int tt = 0; tt < CHUNK; tt++) {
            float hl[3];
            #pragma unroll
            for (int cc = 0; cc < 3; cc++) {
                u64 sA = fma2(whh2[cc][0], hp[0], pack2(xps[tt][cc], 0.0f));
                sA = fma2(whh2[cc][1], hp[1], sA);
                sA = fma2(whh2[cc][2], hp[2], sA);
                u64 sB = fma2(whh2[cc][3], hp[3], ZERO2);
                sB = fma2(whh2[cc][4], hp[4], sB);
                sB = fma2(whh2[cc][5], hp[5], sB);
                hl[cc] = tanh_fast(hadd2(add2(sA, sB)));
            }
            float hs[H_DIM];
            #pragma unroll
            for (int s = 0; s < 4; s++) {
                #pragma unroll
                for (int cc = 0; cc < 3; cc++)
                    hs[s * 3 + cc] = __shfl_sync(0xffffffffu, hl[cc], qbase + s);
            }
            #pragma unroll
            for (int p = 0; p < H_DIM / 2; p++)
                hp[p] = pack2(hs[2 * p], hs[2 * p + 1]);
        }
    }

    // MLP head: one thread per element
    if (sub == 0) {
        float h_all[H_DIM];
        #pragma unroll
        for (int p = 0; p < H_DIM / 2; p++) unpack2(hp[p], h_all[2 * p], h_all[2 * p + 1]);
        float o1[H_DIM], o2[H_DIM];
        #pragma unroll
        for (int j = 0; j < H_DIM; j++) {
            float s = sb1[j];
            #pragma unroll
            for (int k = 0; k < H_DIM; k++) s = fmaf(sW1[j * H_DIM + k], h_all[k], s);
            o1[j] = fmaxf(s, 0.0f);
        }
        #pragma unroll
        for (int j = 0; j < H_DIM; j++) {
            float s = sb2[j];
            #pragma unroll
            for (int k = 0; k < H_DIM; k++) s = fmaf(sW2[j * H_DIM + k], o1[k], s);
            o2[j] = fmaxf(s, 0.0f);
        }
        float s = sb3[0];
        #pragma unroll
        for (int k = 0; k < H_DIM; k++) s = fmaf(sW3[k], o2[k], s);
        out[b] = s;
    }
}

extern "C" void kernel_launch(void* const* d_in, const int* in_sizes, int n_in,
                              void* d_out, int out_size) {
    (void)in_sizes; (void)n_in; (void)out_size;
    const float* x    = (const float*)d_in[0];
    const float* W_ih = (const float*)d_in[1];
    const float* b_ih = (const float*)d_in[2];
    const float* W_hh = (const float*)d_in[3];
    const float* b_hh = (const float*)d_in[4];
    const float* W1   = (const float*)d_in[5];
    const float* b1   = (const float*)d_in[6];
    const float* W2   = (const float*)d_in[7];
    const float* b2   = (const float*)d_in[8];
    const float* W3   = (const float*)d_in[9];
    const float* b3   = (const float*)d_in[10];
    float* out = (float*)d_out;

    cudaFuncSetAttribute(rnn_fused_kernel,
                         cudaFuncAttributeMaxDynamicSharedMemorySize, SMEM_BYTES);

    dim3 grid(B_TOT / EPB);   // 512 blocks
    dim3 block(NTHREADS);     // 64 threads
    rnn_fused_kernel<<<grid, block, SMEM_BYTES>>>(
        x, W_ih, b_ih, W_hh, b_hh, W1, b1, W2, b2, W3, b3, out);
}

// round 4
// speedup vs baseline: 1.0064x; 1.0064x over previous
#include <cuda_runtime.h>

#define B_TOT    8192
#define T_LEN    512
#define F_IN     24
#define H_DIM    12
#define CHUNK    8
#define EPB      8            // batch elements per block
#define TPE      8            // threads per element (2 rows each, rows 8-11 duplicated)
#define NTHREADS (EPB * TPE)  // 64
#define NCHUNK   (T_LEN / CHUNK)
#define XS_STRIDE 28          // padded floats per (tt, elem) row
#define XS_BUF_FLOATS (CHUNK * EPB * XS_STRIDE)
#define SMEM_BYTES (2 * XS_BUF_FLOATS * 4)

typedef unsigned long long u64;

__device__ __forceinline__ unsigned smem_u32(const void* p) {
    return (unsigned)__cvta_generic_to_shared(p);
}
__device__ __forceinline__ void cp_async16(unsigned dst, const void* src) {
    asm volatile("cp.async.cg.shared.global [%0], [%1], 16;\n" :: "r"(dst), "l"(src));
}
__device__ __forceinline__ void cp_commit() {
    asm volatile("cp.async.commit_group;\n" ::: "memory");
}
template <int N> __device__ __forceinline__ void cp_wait() {
    asm volatile("cp.async.wait_group %0;\n" :: "n"(N) : "memory");
}

// ---- packed f32x2 helpers ----
__device__ __forceinline__ u64 pack2(float lo, float hi) {
    u64 d; asm("mov.b64 %0, {%1, %2};" : "=l"(d) : "f"(lo), "f"(hi)); return d;
}
__device__ __forceinline__ void unpack2(u64 d, float& lo, float& hi) {
    asm("mov.b64 {%0, %1}, %2;" : "=f"(lo), "=f"(hi) : "l"(d));
}
__device__ __forceinline__ u64 fma2(u64 a, u64 b, u64 c) {
    u64 d; asm("fma.rn.f32x2 %0, %1, %2, %3;" : "=l"(d) : "l"(a), "l"(b), "l"(c)); return d;
}
__device__ __forceinline__ u64 add2(u64 a, u64 b) {
    u64 d; asm("add.rn.f32x2 %0, %1, %2;" : "=l"(d) : "l"(a), "l"(b)); return d;
}
__device__ __forceinline__ float hadd2(u64 a) {
    float lo, hi; unpack2(a, lo, hi); return lo + hi;
}

// tanh(x) = 1 - 2*rcp(exp(2x)+1); 5 instrs, correct saturation at +/-inf.
__device__ __forceinline__ float tanh_fast(float x) {
    float e;
    asm("ex2.approx.f32 %0, %1;" : "=f"(e) : "f"(x * 2.885390082f));
    float r;
    asm("rcp.approx.f32 %0, %1;" : "=f"(r) : "f"(e + 1.0f));
    return fmaf(-2.0f, r, 1.0f);
}

__global__ void __launch_bounds__(NTHREADS) rnn_fused_kernel(
    const float* __restrict__ x,
    const float* __restrict__ W_ih, const float* __restrict__ b_ih,
    const float* __restrict__ W_hh, const float* __restrict__ b_hh,
    const float* __restrict__ W1,   const float* __restrict__ b1,
    const float* __restrict__ W2,   const float* __restrict__ b2,
    const float* __restrict__ W3,   const float* __restrict__ b3,
    float* __restrict__ out)
{
    extern __shared__ float xs[];  // [2][CHUNK][EPB][XS_STRIDE]
    __shared__ float sW1[144], sW2[144], sb1[12], sb2[12], sW3[12], sb3[1];

    const int tid  = threadIdx.x;
    const int e    = tid >> 3;        // element within block (0..7)
    const int sub  = tid & 7;         // 8 lanes per element
    const int lane = tid & 31;
    const int b    = blockIdx.x * EPB + e;

    // Two rows per thread, uniform across the warp (no divergence):
    //   r0 = sub (rows 0..7), r1 = 8 + (sub & 3) (rows 8..11, duplicated by subs 4..7)
    const int r0 = sub;
    const int r1 = 8 + (sub & 3);

    for (int i = tid; i < 144; i += NTHREADS) { sW1[i] = W1[i]; sW2[i] = W2[i]; }
    if (tid < 12) { sb1[tid] = b1[tid]; sb2[tid] = b2[tid]; sW3[tid] = W3[tid]; }
    if (tid == 0) sb3[0] = b3[0];

    // Per-thread weights for the two rows, packed along contraction dim.
    u64 wih2[2][F_IN / 2], whh2[2][H_DIM / 2], biasp[2];
    {
        const int rows[2] = {r0, r1};
        #pragma unroll
        for (int c = 0; c < 2; c++) {
            const int j = rows[c];
            #pragma unroll
            for (int p = 0; p < F_IN / 2; p++)
                wih2[c][p] = pack2(W_ih[j * F_IN + 2 * p], W_ih[j * F_IN + 2 * p + 1]);
            #pragma unroll
            for (int p = 0; p < H_DIM / 2; p++)
                whh2[c][p] = pack2(W_hh[j * H_DIM + 2 * p], W_hh[j * H_DIM + 2 * p + 1]);
            biasp[c] = pack2(b_ih[j] + b_hh[j], 0.0f);
        }
    }

    // cp.async: thread (e, sub) stages timestep tt=sub of element e (96B = 6x16B).
    const float* src0 = x + ((long)b * T_LEN + sub) * F_IN;
    const unsigned dst0 = smem_u32(xs) + (unsigned)(((sub * EPB + e) * XS_STRIDE) * 4);

    auto load_chunk = [&](int bufidx, int c) {
        const float* s = src0 + (long)c * (CHUNK * F_IN);
        const unsigned d = dst0 + (unsigned)bufidx * (XS_BUF_FLOATS * 4);
        #pragma unroll
        for (int q = 0; q < 6; q++)
            cp_async16(d + (unsigned)(q * 16), s + q * 4);
        cp_commit();
    };

    u64 hp[H_DIM / 2];
    #pragma unroll
    for (int k = 0; k < H_DIM / 2; k++) hp[k] = 0ull;

    const u64 ZERO2 = 0ull;
    const int g = lane & ~7;   // 8-lane group base within warp

    load_chunk(0, 0);

    for (int c = 0; c < NCHUNK; c++) {
        __syncthreads();  // everyone done reading the buffer we overwrite
        if (c + 1 < NCHUNK) { load_chunk((c + 1) & 1, c + 1); cp_wait<1>(); }
        else                { cp_wait<0>(); }
        __syncthreads();  // buf[c&1] visible

        const float* buf = xs + (c & 1) * XS_BUF_FLOATS;

        #pragma unroll
        for (int tt = 0; tt < CHUNK; tt++) {
            // x row: 6 conflict-free LDS.128, shared by both of this thread's rows
            const ulonglong2* xr = (const ulonglong2*)(buf + (tt * EPB + e) * XS_STRIDE);
            u64 a0 = biasp[0], a1 = biasp[1];
            #pragma unroll
            for (int q = 0; q < 6; q++) {
                ulonglong2 v = xr[q];
                a0 = fma2(wih2[0][2 * q + 0], v.x, a0);
                a1 = fma2(wih2[1][2 * q + 0], v.x, a1);
                a0 = fma2(wih2[0][2 * q + 1], v.y, a0);
                a1 = fma2(wih2[1][2 * q + 1], v.y, a1);
            }
            // recurrence: split accumulators to shorten the dependent chain
            u64 sB0 = fma2(whh2[0][3], hp[3], ZERO2);
            u64 sB1 = fma2(whh2[1][3], hp[3], ZERO2);
            a0 = fma2(whh2[0][0], hp[0], a0);
            a1 = fma2(whh2[1][0], hp[0], a1);
            sB0 = fma2(whh2[0][4], hp[4], sB0);
            sB1 = fma2(whh2[1][4], hp[4], sB1);
            a0 = fma2(whh2[0][1], hp[1], a0);
            a1 = fma2(whh2[1][1], hp[1], a1);
            sB0 = fma2(whh2[0][5], hp[5], sB0);
            sB1 = fma2(whh2[1][5], hp[5], sB1);
            a0 = fma2(whh2[0][2], hp[2], a0);
            a1 = fma2(whh2[1][2], hp[2], a1);

            float hl0 = tanh_fast(hadd2(add2(a0, sB0)));
            float hl1 = tanh_fast(hadd2(add2(a1, sB1)));

            // gather h_all for this element: rows 0..7 from lanes g+0..7 (hl0),
            // rows 8..11 from lanes g+0..3 (hl1)
            float hs[H_DIM];
            #pragma unroll
            for (int k = 0; k < 8; k++)
                hs[k] = __shfl_sync(0xffffffffu, hl0, g + k);
            #pragma unroll
            for (int k = 0; k < 4; k++)
                hs[8 + k] = __shfl_sync(0xffffffffu, hl1, g + k);
            #pragma unroll
            for (int p = 0; p < H_DIM / 2; p++)
                hp[p] = pack2(hs[2 * p], hs[2 * p + 1]);
        }
    }

    // MLP head: one thread per element
    if (sub == 0) {
        float h_all[H_DIM];
        #pragma unroll
        for (int p = 0; p < H_DIM / 2; p++) unpack2(hp[p], h_all[2 * p], h_all[2 * p + 1]);
        float o1[H_DIM], o2[H_DIM];
        #pragma unroll
        for (int j = 0; j < H_DIM; j++) {
            float s = sb1[j];
            #pragma unroll
            for (int k = 0; k < H_DIM; k++) s = fmaf(sW1[j * H_DIM + k], h_all[k], s);
            o1[j] = fmaxf(s, 0.0f);
        }
        #pragma unroll
        for (int j = 0; j < H_DIM; j++) {
            float s = sb2[j];
            #pragma unroll
            for (int k = 0; k < H_DIM; k++) s = fmaf(sW2[j * H_DIM + k], o1[k], s);
            o2[j] = fmaxf(s, 0.0f);
        }
        float s = sb3[0];
        #pragma unroll
        for (int k = 0; k < H_DIM; k++) s = fmaf(sW3[k], o2[k], s);
        out[b] = s;
    }
}

extern "C" void kernel_launch(void* const* d_in, const int* in_sizes, int n_in,
                              void* d_out, int out_size) {
    (void)in_sizes; (void)n_in; (void)out_size;
    const float* x    = (const float*)d_in[0];
    const float* W_ih = (const float*)d_in[1];
    const float* b_ih = (const float*)d_in[2];
    const float* W_hh = (const float*)d_in[3];
    const float* b_hh = (const float*)d_in[4];
    const float* W1   = (const float*)d_in[5];
    const float* b1   = (const float*)d_in[6];
    const float* W2   = (const float*)d_in[7];
    const float* b2   = (const float*)d_in[8];
    const float* W3   = (const float*)d_in[9];
    const float* b3   = (const float*)d_in[10];
    float* out = (float*)d_out;

    cudaFuncSetAttribute(rnn_fused_kernel,
                         cudaFuncAttributeMaxDynamicSharedMemorySize, SMEM_BYTES);

    dim3 grid(B_TOT / EPB);   // 1024 blocks
    dim3 block(NTHREADS);     // 64 threads
    rnn_fused_kernel<<<grid, block, SMEM_BYTES>>>(
        x, W_ih, b_ih, W_hh, b_hh, W1, b1, W2, b2, W3, b3, out);
}

// round 5
// speedup vs baseline: 1.3076x; 1.2993x over previous
#include <cuda_runtime.h>

#define B_TOT    8192
#define T_LEN    512
#define F_IN     24
#define H_DIM    12
#define CHUNK    8
#define EPB      8            // batch elements per block (one warp)
#define NTHREADS 32           // single-warp blocks
#define NCHUNK   (T_LEN / CHUNK)
#define XS_STRIDE 28          // floats per (tt, elem) row; conflict-free for 8 elems
#define H_STRIDE  20          // floats per elem in h buffer; conflict-free for 8 elems
#define XS_BUF_FLOATS (CHUNK * EPB * XS_STRIDE)   // 1792
#define SMEM_BYTES (2 * XS_BUF_FLOATS * 4)        // 14336

typedef unsigned long long u64;

__device__ __forceinline__ unsigned smem_u32(const void* p) {
    return (unsigned)__cvta_generic_to_shared(p);
}
__device__ __forceinline__ void cp_async16(unsigned dst, const void* src) {
    asm volatile("cp.async.cg.shared.global [%0], [%1], 16;\n" :: "r"(dst), "l"(src));
}
__device__ __forceinline__ void cp_commit() {
    asm volatile("cp.async.commit_group;\n" ::: "memory");
}
template <int N> __device__ __forceinline__ void cp_wait() {
    asm volatile("cp.async.wait_group %0;\n" :: "n"(N) : "memory");
}

// ---- packed f32x2 helpers ----
__device__ __forceinline__ u64 pack2(float lo, float hi) {
    u64 d; asm("mov.b64 %0, {%1, %2};" : "=l"(d) : "f"(lo), "f"(hi)); return d;
}
__device__ __forceinline__ void unpack2(u64 d, float& lo, float& hi) {
    asm("mov.b64 {%0, %1}, %2;" : "=f"(lo), "=f"(hi) : "l"(d));
}
__device__ __forceinline__ u64 fma2(u64 a, u64 b, u64 c) {
    u64 d; asm("fma.rn.f32x2 %0, %1, %2, %3;" : "=l"(d) : "l"(a), "l"(b), "l"(c)); return d;
}
__device__ __forceinline__ u64 add2(u64 a, u64 b) {
    u64 d; asm("add.rn.f32x2 %0, %1, %2;" : "=l"(d) : "l"(a), "l"(b)); return d;
}
__device__ __forceinline__ float hadd2(u64 a) {
    float lo, hi; unpack2(a, lo, hi); return lo + hi;
}

// tanh(x) = 1 - 2*rcp(exp(2x)+1); 5 instrs, correct saturation at +/-inf.
__device__ __forceinline__ float tanh_fast(float x) {
    float e;
    asm("ex2.approx.f32 %0, %1;" : "=f"(e) : "f"(x * 2.885390082f));
    float r;
    asm("rcp.approx.f32 %0, %1;" : "=f"(r) : "f"(e + 1.0f));
    return fmaf(-2.0f, r, 1.0f);
}

__global__ void __launch_bounds__(NTHREADS) rnn_fused_kernel(
    const float* __restrict__ x,
    const float* __restrict__ W_ih, const float* __restrict__ b_ih,
    const float* __restrict__ W_hh, const float* __restrict__ b_hh,
    const float* __restrict__ W1,   const float* __restrict__ b1,
    const float* __restrict__ W2,   const float* __restrict__ b2,
    const float* __restrict__ W3,   const float* __restrict__ b3,
    float* __restrict__ out)
{
    extern __shared__ float xs[];                 // [2][CHUNK][EPB][XS_STRIDE]
    __shared__ float hsm[EPB * H_STRIDE];         // h state, conflict-free stride
    __shared__ float sW1[144], sW2[144], sb1[12], sb2[12], sW3[12], sb3[1];

    const int tid  = threadIdx.x;
    const int e    = tid >> 2;        // element within block (0..7)
    const int sub  = tid & 3;         // 4 lanes per element, 3 h-rows each
    const int b    = blockIdx.x * EPB + e;
    const int j0   = sub * 3;

    for (int i = tid; i < 144; i += NTHREADS) { sW1[i] = W1[i]; sW2[i] = W2[i]; }
    if (tid < 12) { sb1[tid] = b1[tid]; sb2[tid] = b2[tid]; sW3[tid] = W3[tid]; }
    if (tid == 0) sb3[0] = b3[0];

    // zero h state (each thread its own 3 slots)
    hsm[e * H_STRIDE + j0 + 0] = 0.0f;
    hsm[e * H_STRIDE + j0 + 1] = 0.0f;
    hsm[e * H_STRIDE + j0 + 2] = 0.0f;

    // Per-thread weights for rows j0..j0+2, packed along contraction dim.
    u64 wih2[3][F_IN / 2], whh2[3][H_DIM / 2], biasp[3];
    #pragma unroll
    for (int c = 0; c < 3; c++) {
        const int j = j0 + c;
        #pragma unroll
        for (int p = 0; p < F_IN / 2; p++)
            wih2[c][p] = pack2(W_ih[j * F_IN + 2 * p], W_ih[j * F_IN + 2 * p + 1]);
        #pragma unroll
        for (int p = 0; p < H_DIM / 2; p++)
            whh2[c][p] = pack2(W_hh[j * H_DIM + 2 * p], W_hh[j * H_DIM + 2 * p + 1]);
        biasp[c] = pack2(b_ih[j] + b_hh[j], 0.0f);
    }

    // cp.async staging: thread (e,sub) loads timesteps {sub, sub+4} of elem e.
    // 12 x 16B per thread per chunk.
    const float* src0 = x + ((long)b * T_LEN + sub) * F_IN;          // tt = sub
    const unsigned xsb = smem_u32(xs);
    const unsigned dst0 = xsb + (unsigned)(((sub * EPB + e) * XS_STRIDE) * 4);
    const unsigned dstH = xsb + (unsigned)((((sub + 4) * EPB + e) * XS_STRIDE) * 4);

    auto load_chunk = [&](int bufidx, int c) {
        const float* s = src0 + (long)c * (CHUNK * F_IN);
        const unsigned boff = (unsigned)bufidx * (XS_BUF_FLOATS * 4);
        #pragma unroll
        for (int q = 0; q < 6; q++) {
            cp_async16(dst0 + boff + (unsigned)(q * 16), s + q * 4);
            cp_async16(dstH + boff + (unsigned)(q * 16), s + 4 * F_IN + q * 4);
        }
        cp_commit();
    };

    float* hrow = hsm + e * H_STRIDE;   // 16B-aligned (80B stride)
    const float* hW = hsm + e * H_STRIDE + j0;  // this thread's write slots

    load_chunk(0, 0);

    for (int c = 0; c < NCHUNK; c++) {
        if (c + 1 < NCHUNK) { load_chunk((c + 1) & 1, c + 1); cp_wait<1>(); }
        else                { cp_wait<0>(); }
        __syncwarp();  // all lanes' groups for chunk c complete & visible

        const float* buf = xs + (c & 1) * XS_BUF_FLOATS;

        #pragma unroll
        for (int tt = 0; tt < CHUNK; tt++) {
            // x row: 6 conflict-free LDS.128 (pairs come pre-packed for FFMA2)
            const ulonglong2* xr = (const ulonglong2*)(buf + (tt * EPB + e) * XS_STRIDE);
            u64 a0 = biasp[0], a1 = biasp[1], a2 = biasp[2];
            #pragma unroll
            for (int q = 0; q < 6; q++) {
                ulonglong2 v = xr[q];
                a0 = fma2(wih2[0][2 * q + 0], v.x, a0);
                a1 = fma2(wih2[1][2 * q + 0], v.x, a1);
                a2 = fma2(wih2[2][2 * q + 0], v.x, a2);
                a0 = fma2(wih2[0][2 * q + 1], v.y, a0);
                a1 = fma2(wih2[1][2 * q + 1], v.y, a1);
                a2 = fma2(wih2[2][2 * q + 1], v.y, a2);
            }
            // h pairs straight from shared: 3 LDS.128 -> 6 packed f32x2
            const ulonglong2* hr2 = (const ulonglong2*)hrow;
            ulonglong2 hv0 = hr2[0];   // (h0,h1),(h2,h3)
            ulonglong2 hv1 = hr2[1];   // (h4,h5),(h6,h7)
            ulonglong2 hv2 = hr2[2];   // (h8,h9),(h10,h11)

            u64 s0 = fma2(whh2[0][0], hv0.x, a0);
            u64 s1 = fma2(whh2[1][0], hv0.x, a1);
            u64 s2 = fma2(whh2[2][0], hv0.x, a2);
            u64 t0 = fma2(whh2[0][3], hv1.y, (u64)0);
            u64 t1 = fma2(whh2[1][3], hv1.y, (u64)0);
            u64 t2 = fma2(whh2[2][3], hv1.y, (u64)0);
            s0 = fma2(whh2[0][1], hv0.y, s0);
            s1 = fma2(whh2[1][1], hv0.y, s1);
            s2 = fma2(whh2[2][1], hv0.y, s2);
            t0 = fma2(whh2[0][4], hv2.x, t0);
            t1 = fma2(whh2[1][4], hv2.x, t1);
            t2 = fma2(whh2[2][4], hv2.x, t2);
            s0 = fma2(whh2[0][2], hv1.x, s0);
            s1 = fma2(whh2[1][2], hv1.x, s1);
            s2 = fma2(whh2[2][2], hv1.x, s2);
            t0 = fma2(whh2[0][5], hv2.y, t0);
            t1 = fma2(whh2[1][5], hv2.y, t1);
            t2 = fma2(whh2[2][5], hv2.y, t2);

            float hl0 = tanh_fast(hadd2(add2(s0, t0)));
            float hl1 = tanh_fast(hadd2(add2(s1, t1)));
            float hl2 = tanh_fast(hadd2(add2(s2, t2)));

            // publish h: 3 conflict-free STS.32, then warp-visible
            __syncwarp();                 // all lanes done reading old h
            const_cast<float*>(hW)[0] = hl0;
            const_cast<float*>(hW)[1] = hl1;
            const_cast<float*>(hW)[2] = hl2;
            __syncwarp();                 // new h visible to all lanes
        }
    }

    // MLP head: one thread per element (reads final h from shared)
    if (sub == 0) {
        float h_all[H_DIM];
        #pragma unroll
        for (int k = 0; k < H_DIM; k++) h_all[k] = hrow[k];
        float o1[H_DIM], o2[H_DIM];
        #pragma unroll
        for (int j = 0; j < H_DIM; j++) {
            float s = sb1[j];
            #pragma unroll
            for (int k = 0; k < H_DIM; k++) s = fmaf(sW1[j * H_DIM + k], h_all[k], s);
            o1[j] = fmaxf(s, 0.0f);
        }
        #pragma unroll
        for (int j = 0; j < H_DIM; j++) {
            float s = sb2[j];
            #pragma unroll
            for (int k = 0; k < H_DIM; k++) s = fmaf(sW2[j * H_DIM + k], o1[k], s);
            o2[j] = fmaxf(s, 0.0f);
        }
        float s = sb3[0];
        #pragma unroll
        for (int k = 0; k < H_DIM; k++) s = fmaf(sW3[k], o2[k], s);
        out[b] = s;
    }
}

extern "C" void kernel_launch(void* const* d_in, const int* in_sizes, int n_in,
                              void* d_out, int out_size) {
    (void)in_sizes; (void)n_in; (void)out_size;
    const float* x    = (const float*)d_in[0];
    const float* W_ih = (const float*)d_in[1];
    const float* b_ih = (const float*)d_in[2];
    const float* W_hh = (const float*)d_in[3];
    const float* b_hh = (const float*)d_in[4];
    const float* W1   = (const float*)d_in[5];
    const float* b1   = (const float*)d_in[6];
    const float* W2   = (const float*)d_in[7];
    const float* b2   = (const float*)d_in[8];
    const float* W3   = (const float*)d_in[9];
    const float* b3   = (const float*)d_in[10];
    float* out = (float*)d_out;

    cudaFuncSetAttribute(rnn_fused_kernel,
                         cudaFuncAttributeMaxDynamicSharedMemorySize, SMEM_BYTES);

    dim3 grid(B_TOT / EPB);   // 1024 single-warp blocks
    dim3 block(NTHREADS);     // 32 threads
    rnn_fused_kernel<<<grid, block, SMEM_BYTES>>>(
        x, W_ih, b_ih, W_hh, b_hh, W1, b1, W2, b2, W3, b3, out);
}